// round 1
// baseline (speedup 1.0000x reference)
#include <cuda_runtime.h>
#include <cuda_bf16.h>
#include <math.h>

#define NN 30000
#define EE 480000
#define F_IN 100
#define HID 64
#define HEADS 4
#define NCLS 47
#define HC 256           // HEADS*HID
#define L2OUT 188        // HEADS*NCLS

// ---------------- scratch (device globals; no allocs allowed) ----------------
__device__ float g_h[(size_t)NN * HC];      // GAT linear output (no bias); layer2 uses NN*188
__device__ float g_skip[(size_t)NN * HC];   // skip GEMM output (+bias); layer2 uses NN*47
__device__ float g_agg[(size_t)NN * HC];    // aggregated GAT output / pre-BN; layer2 NN*47
__device__ float g_hcur[(size_t)NN * HC];   // layer input after BN+ELU
__device__ float g_als[(size_t)NN * HEADS];
__device__ float g_ald[(size_t)NN * HEADS];
__device__ float g_den[(size_t)NN * HEADS];
__device__ float g_ealpha[(size_t)EE * HEADS];
__device__ float g_bnsum[2 * HC];

// ---------------- helpers ----------------
__device__ __forceinline__ void red_add_v4(float* addr, float a, float b, float c, float d) {
    asm volatile("red.global.add.v4.f32 [%0], {%1,%2,%3,%4};"
                 :: "l"(addr), "f"(a), "f"(b), "f"(c), "f"(d) : "memory");
}

__device__ __forceinline__ float lrelu(float x) { return x > 0.f ? x : 0.2f * x; }

// ---------------- GEMM: C[M,Ncol] = A[M,K] @ B[K,Ncol] (+bias) ----------------
__global__ __launch_bounds__(256) void sgemm_kernel(
    const float* __restrict__ A, const float* __restrict__ B,
    const float* __restrict__ bias, float* __restrict__ C,
    int M, int K, int Ncol)
{
    const int BM = 128, BN = 128, BK = 8, TM = 8, TN = 8;
    __shared__ float As[BK][BM];
    __shared__ float Bs[BK][BN];
    int tid = threadIdx.x;
    int rowBlock = blockIdx.y * BM;
    int colBlock = blockIdx.x * BN;
    int trow = (tid / 16) * TM;
    int tcol = (tid % 16) * TN;
    float acc[TM][TN];
#pragma unroll
    for (int i = 0; i < TM; i++)
#pragma unroll
        for (int j = 0; j < TN; j++) acc[i][j] = 0.f;

    for (int k0 = 0; k0 < K; k0 += BK) {
#pragma unroll
        for (int i = tid; i < BM * BK; i += 256) {
            int r = i / BK, kk = i % BK;
            int gr = rowBlock + r, gk = k0 + kk;
            As[kk][r] = (gr < M && gk < K) ? A[(size_t)gr * K + gk] : 0.f;
        }
#pragma unroll
        for (int i = tid; i < BK * BN; i += 256) {
            int kk = i / BN, c = i % BN;
            int gk = k0 + kk, gc = colBlock + c;
            Bs[kk][c] = (gk < K && gc < Ncol) ? B[(size_t)gk * Ncol + gc] : 0.f;
        }
        __syncthreads();
#pragma unroll
        for (int kk = 0; kk < BK; kk++) {
            float a[TM], b[TN];
#pragma unroll
            for (int i = 0; i < TM; i++) a[i] = As[kk][trow + i];
#pragma unroll
            for (int j = 0; j < TN; j++) b[j] = Bs[kk][tcol + j];
#pragma unroll
            for (int i = 0; i < TM; i++)
#pragma unroll
                for (int j = 0; j < TN; j++) acc[i][j] = fmaf(a[i], b[j], acc[i][j]);
        }
        __syncthreads();
    }
#pragma unroll
    for (int i = 0; i < TM; i++) {
        int gr = rowBlock + trow + i;
        if (gr >= M) continue;
#pragma unroll
        for (int j = 0; j < TN; j++) {
            int gc = colBlock + tcol + j;
            if (gc >= Ncol) continue;
            float v = acc[i][j];
            if (bias) v += bias[gc];
            C[(size_t)gr * Ncol + gc] = v;
        }
    }
}

// ---------------- per-(node,head) attention logits ----------------
__global__ void al_kernel(const float* __restrict__ h, const float* __restrict__ a_s,
                          const float* __restrict__ a_d, float* __restrict__ als,
                          float* __restrict__ ald, int C)
{
    int w = (blockIdx.x * blockDim.x + threadIdx.x) >> 5;
    int lane = threadIdx.x & 31;
    if (w >= NN * HEADS) return;
    int n = w >> 2, hd = w & 3;
    const float* hp = h + (size_t)n * (HEADS * C) + hd * C;
    float ss = 0.f, sd = 0.f;
    for (int c = lane; c < C; c += 32) {
        float v = hp[c];
        ss = fmaf(v, a_s[hd * C + c], ss);
        sd = fmaf(v, a_d[hd * C + c], sd);
    }
#pragma unroll
    for (int o = 16; o; o >>= 1) {
        ss += __shfl_xor_sync(0xffffffffu, ss, o);
        sd += __shfl_xor_sync(0xffffffffu, sd, o);
    }
    if (lane == 0) { als[w] = ss; ald[w] = sd; }
}

// ---------------- edge pass 1: exp + denominator ----------------
__global__ void edge_expsum_kernel(const int* __restrict__ src, const int* __restrict__ dst,
                                   const float4* __restrict__ als, const float4* __restrict__ ald,
                                   float4* __restrict__ ealpha, float* __restrict__ den)
{
    int e = blockIdx.x * blockDim.x + threadIdx.x;
    if (e >= EE) return;
    int s = src[e], d = dst[e];
    float4 a = als[s], b = ald[d];
    float4 t;
    t.x = expf(lrelu(a.x + b.x));
    t.y = expf(lrelu(a.y + b.y));
    t.z = expf(lrelu(a.z + b.z));
    t.w = expf(lrelu(a.w + b.w));
    ealpha[e] = t;
    red_add_v4(den + (size_t)d * 4, t.x, t.y, t.z, t.w);
}

// ---------------- edge pass 2: weighted scatter (layers 0/1, C=64/head) -------
__global__ void edge_agg_kernel(const int* __restrict__ src, const int* __restrict__ dst,
                                const float* __restrict__ h, const float4* __restrict__ ealpha,
                                const float4* __restrict__ den, float* __restrict__ out)
{
    int w = (blockIdx.x * blockDim.x + threadIdx.x) >> 5;
    int lane = threadIdx.x & 31;
    if (w >= EE) return;
    int s = src[w], d = dst[w];
    float4 ea = ealpha[w];
    float4 dn = den[d];
    float al4[4];
    al4[0] = ea.x / (dn.x + 1e-16f);
    al4[1] = ea.y / (dn.y + 1e-16f);
    al4[2] = ea.z / (dn.z + 1e-16f);
    al4[3] = ea.w / (dn.w + 1e-16f);
    float alpha = al4[lane >> 3];
    const float4* hp = reinterpret_cast<const float4*>(h + (size_t)s * HC) + lane * 2;
    float4 v0 = hp[0], v1 = hp[1];
    float* op = out + (size_t)d * HC + lane * 8;
    red_add_v4(op,     v0.x * alpha, v0.y * alpha, v0.z * alpha, v0.w * alpha);
    red_add_v4(op + 4, v1.x * alpha, v1.y * alpha, v1.z * alpha, v1.w * alpha);
}

// ---------------- edge pass 2 for layer 2 (sum over heads, 47 out ch) --------
__global__ void edge_agg47_kernel(const int* __restrict__ src, const int* __restrict__ dst,
                                  const float* __restrict__ h, const float4* __restrict__ ealpha,
                                  const float4* __restrict__ den, float* __restrict__ out)
{
    int w = (blockIdx.x * blockDim.x + threadIdx.x) >> 5;
    int lane = threadIdx.x & 31;
    if (w >= EE) return;
    int s = src[w], d = dst[w];
    float4 ea = ealpha[w];
    float4 dn = den[d];
    float a0 = ea.x / (dn.x + 1e-16f);
    float a1 = ea.y / (dn.y + 1e-16f);
    float a2 = ea.z / (dn.z + 1e-16f);
    float a3 = ea.w / (dn.w + 1e-16f);
    const float* hs = h + (size_t)s * L2OUT;
    for (int c = lane; c < NCLS; c += 32) {
        float v = a0 * hs[c] + a1 * hs[NCLS + c] + a2 * hs[2 * NCLS + c] + a3 * hs[3 * NCLS + c];
        atomicAdd(out + (size_t)d * NCLS + c, v);
    }
}

// ---------------- BN stats: pre = agg + bias + skip; accumulate sums ---------
__global__ void bn_stats_kernel(float* __restrict__ agg, const float* __restrict__ skip,
                                const float* __restrict__ bias, float* __restrict__ sums)
{
    int c = threadIdx.x;           // 256 channels
    float b = bias[c];
    float s = 0.f, s2 = 0.f;
    for (int r = blockIdx.x; r < NN; r += gridDim.x) {
        size_t idx = (size_t)r * HC + c;
        float v = agg[idx] + b + skip[idx];
        agg[idx] = v;
        s += v;
        s2 = fmaf(v, v, s2);
    }
    atomicAdd(&sums[c], s);
    atomicAdd(&sums[HC + c], s2);
}

// ---------------- BN apply + ELU ----------------
__global__ void bn_apply_kernel(const float* __restrict__ pre, const float* __restrict__ sums,
                                const float* __restrict__ gamma, const float* __restrict__ beta,
                                float* __restrict__ outp)
{
    int c = threadIdx.x;
    float mu = sums[c] * (1.f / NN);
    float var = sums[HC + c] * (1.f / NN) - mu * mu;
    float rstd = rsqrtf(var + 1e-5f);
    float g = gamma[c] * rstd;
    float b = beta[c] - mu * g;
    for (int r = blockIdx.x; r < NN; r += gridDim.x) {
        size_t idx = (size_t)r * HC + c;
        float v = fmaf(pre[idx], g, b);
        outp[idx] = v > 0.f ? v : expf(v) - 1.f;
    }
}

// ---------------- final: mean over heads + bias + skip + log_softmax ---------
__global__ void final_kernel(const float* __restrict__ agg47, const float* __restrict__ skip47,
                             const float* __restrict__ b2, float* __restrict__ out)
{
    int w = (blockIdx.x * blockDim.x + threadIdx.x) >> 5;
    int lane = threadIdx.x & 31;
    if (w >= NN) return;
    int c0 = lane, c1 = lane + 32;
    float v0 = -1e30f, v1 = -1e30f;
    if (c0 < NCLS) v0 = agg47[(size_t)w * NCLS + c0] * 0.25f + b2[c0] + skip47[(size_t)w * NCLS + c0];
    if (c1 < NCLS) v1 = agg47[(size_t)w * NCLS + c1] * 0.25f + b2[c1] + skip47[(size_t)w * NCLS + c1];
    float m = fmaxf(v0, v1);
#pragma unroll
    for (int o = 16; o; o >>= 1) m = fmaxf(m, __shfl_xor_sync(0xffffffffu, m, o));
    float s = 0.f;
    if (c0 < NCLS) s += expf(v0 - m);
    if (c1 < NCLS) s += expf(v1 - m);
#pragma unroll
    for (int o = 16; o; o >>= 1) s += __shfl_xor_sync(0xffffffffu, s, o);
    float lse = m + logf(s);
    if (c0 < NCLS) out[(size_t)w * NCLS + c0] = v0 - lse;
    if (c1 < NCLS) out[(size_t)w * NCLS + c1] = v1 - lse;
}

// ---------------- host orchestration ----------------
extern "C" void kernel_launch(void* const* d_in, const int* in_sizes, int n_in,
                              void* d_out, int out_size)
{
    const float* x   = (const float*)d_in[0];
    const int*   ei  = (const int*)d_in[1];
    const float* w0  = (const float*)d_in[2];
    const float* as0 = (const float*)d_in[3];
    const float* ad0 = (const float*)d_in[4];
    const float* b0  = (const float*)d_in[5];
    const float* sw0 = (const float*)d_in[6];
    const float* sb0 = (const float*)d_in[7];
    const float* g0  = (const float*)d_in[8];
    const float* be0 = (const float*)d_in[9];
    const float* w1  = (const float*)d_in[10];
    const float* as1 = (const float*)d_in[11];
    const float* ad1 = (const float*)d_in[12];
    const float* b1  = (const float*)d_in[13];
    const float* sw1 = (const float*)d_in[14];
    const float* sb1 = (const float*)d_in[15];
    const float* g1  = (const float*)d_in[16];
    const float* be1 = (const float*)d_in[17];
    const float* w2  = (const float*)d_in[18];
    const float* as2 = (const float*)d_in[19];
    const float* ad2 = (const float*)d_in[20];
    const float* b2  = (const float*)d_in[21];
    const float* sw2 = (const float*)d_in[22];
    const float* sb2 = (const float*)d_in[23];

    const int* src = ei;
    const int* dst = ei + EE;

    float *h, *skip, *agg, *hcur, *als, *ald, *den, *ealpha, *bnsum;
    cudaGetSymbolAddress((void**)&h, g_h);
    cudaGetSymbolAddress((void**)&skip, g_skip);
    cudaGetSymbolAddress((void**)&agg, g_agg);
    cudaGetSymbolAddress((void**)&hcur, g_hcur);
    cudaGetSymbolAddress((void**)&als, g_als);
    cudaGetSymbolAddress((void**)&ald, g_ald);
    cudaGetSymbolAddress((void**)&den, g_den);
    cudaGetSymbolAddress((void**)&ealpha, g_ealpha);
    cudaGetSymbolAddress((void**)&bnsum, g_bnsum);

    dim3 gemmGrid256(2, (NN + 127) / 128);   // Ncol=256
    dim3 gemmGrid188(2, (NN + 127) / 128);   // Ncol=188
    dim3 gemmGrid47(1, (NN + 127) / 128);    // Ncol=47
    int alBlocks = (NN * HEADS * 32 + 255) / 256;
    int eThreadBlocks = (EE + 255) / 256;
    int eWarpBlocks = (EE * 32 + 255) / 256;

    // ===== Layer 0 =====
    sgemm_kernel<<<gemmGrid256, 256>>>(x, w0, nullptr, h, NN, F_IN, HC);
    sgemm_kernel<<<gemmGrid256, 256>>>(x, sw0, sb0, skip, NN, F_IN, HC);
    al_kernel<<<alBlocks, 256>>>(h, as0, ad0, als, ald, HID);
    cudaMemsetAsync(den, 0, (size_t)NN * HEADS * sizeof(float));
    cudaMemsetAsync(agg, 0, (size_t)NN * HC * sizeof(float));
    edge_expsum_kernel<<<eThreadBlocks, 256>>>(src, dst, (const float4*)als, (const float4*)ald,
                                               (float4*)ealpha, den);
    edge_agg_kernel<<<eWarpBlocks, 256>>>(src, dst, h, (const float4*)ealpha, (const float4*)den, agg);
    cudaMemsetAsync(bnsum, 0, 2 * HC * sizeof(float));
    bn_stats_kernel<<<512, 256>>>(agg, skip, b0, bnsum);
    bn_apply_kernel<<<512, 256>>>(agg, bnsum, g0, be0, hcur);

    // ===== Layer 1 =====
    sgemm_kernel<<<gemmGrid256, 256>>>(hcur, w1, nullptr, h, NN, HC, HC);
    sgemm_kernel<<<gemmGrid256, 256>>>(hcur, sw1, sb1, skip, NN, HC, HC);
    al_kernel<<<alBlocks, 256>>>(h, as1, ad1, als, ald, HID);
    cudaMemsetAsync(den, 0, (size_t)NN * HEADS * sizeof(float));
    cudaMemsetAsync(agg, 0, (size_t)NN * HC * sizeof(float));
    edge_expsum_kernel<<<eThreadBlocks, 256>>>(src, dst, (const float4*)als, (const float4*)ald,
                                               (float4*)ealpha, den);
    edge_agg_kernel<<<eWarpBlocks, 256>>>(src, dst, h, (const float4*)ealpha, (const float4*)den, agg);
    cudaMemsetAsync(bnsum, 0, 2 * HC * sizeof(float));
    bn_stats_kernel<<<512, 256>>>(agg, skip, b1, bnsum);
    bn_apply_kernel<<<512, 256>>>(agg, bnsum, g1, be1, hcur);

    // ===== Layer 2 =====
    sgemm_kernel<<<gemmGrid188, 256>>>(hcur, w2, nullptr, h, NN, HC, L2OUT);
    sgemm_kernel<<<gemmGrid47, 256>>>(hcur, sw2, sb2, skip, NN, HC, NCLS);
    al_kernel<<<alBlocks, 256>>>(h, as2, ad2, als, ald, NCLS);
    cudaMemsetAsync(den, 0, (size_t)NN * HEADS * sizeof(float));
    cudaMemsetAsync(agg, 0, (size_t)NN * NCLS * sizeof(float));
    edge_expsum_kernel<<<eThreadBlocks, 256>>>(src, dst, (const float4*)als, (const float4*)ald,
                                               (float4*)ealpha, den);
    edge_agg47_kernel<<<eWarpBlocks, 256>>>(src, dst, h, (const float4*)ealpha, (const float4*)den, agg);
    final_kernel<<<(NN * 32 + 255) / 256, 256>>>(agg, skip, b2, (float*)d_out);
}

// round 2
// speedup vs baseline: 1.5609x; 1.5609x over previous
#include <cuda_runtime.h>
#include <cuda_bf16.h>
#include <math.h>

#define NN 30000
#define EE 480000
#define F_IN 100
#define HID 64
#define HEADS 4
#define NCLS 47
#define HC 256           // HEADS*HID
#define L2OUT 188        // HEADS*NCLS
#define NP2 240          // padded pack width for layer 2 (188+47 -> 240)

// ---------------- scratch (device globals; no allocs allowed) ----------------
__device__ __align__(16) float g_h[(size_t)NN * HC];      // GAT linear output
__device__ __align__(16) float g_skip[(size_t)NN * HC];   // skip GEMM output (+sbias)
__device__ __align__(16) float g_agg[(size_t)NN * HC];    // pre-BN (= msg + bias + skip)
__device__ __align__(16) float g_hcur[(size_t)NN * HC];   // layer input after BN+ELU
__device__ __align__(16) float g_als[(size_t)NN * HEADS];
__device__ __align__(16) float g_ald[(size_t)NN * HEADS];
__device__ float g_bnsum[2 * HC];
// CSR
__device__ int g_cnt[NN];
__device__ int g_rowptr[NN + 1];
__device__ int g_cursor[NN];
__device__ int g_csrc[EE];
// packed weights
__device__ __align__(16) float g_p0[F_IN * 512];
__device__ __align__(16) float g_p1[HC * 512];
__device__ __align__(16) float g_p2[HC * NP2];

__device__ __forceinline__ float lrelu(float x) { return x > 0.f ? x : 0.2f * x; }

// ---------------- pack [W | SW] per layer (done every call; tiny) ------------
__global__ void pack_weights(const float* __restrict__ w0, const float* __restrict__ sw0,
                             const float* __restrict__ w1, const float* __restrict__ sw1,
                             const float* __restrict__ w2, const float* __restrict__ sw2,
                             float* __restrict__ p0, float* __restrict__ p1, float* __restrict__ p2)
{
    int tid = blockIdx.x * blockDim.x + threadIdx.x;
    int stride = gridDim.x * blockDim.x;
    for (int i = tid; i < F_IN * 512; i += stride) {
        int k = i / 512, c = i % 512;
        p0[i] = (c < HC) ? w0[k * HC + c] : sw0[k * HC + (c - HC)];
    }
    for (int i = tid; i < HC * 512; i += stride) {
        int k = i / 512, c = i % 512;
        p1[i] = (c < HC) ? w1[k * HC + c] : sw1[k * HC + (c - HC)];
    }
    for (int i = tid; i < HC * NP2; i += stride) {
        int k = i / NP2, c = i % NP2;
        float v = 0.f;
        if (c < L2OUT) v = w2[k * L2OUT + c];
        else if (c < L2OUT + NCLS) v = sw2[k * NCLS + (c - L2OUT)];
        p2[i] = v;
    }
}

// ---------------- CSR build ----------------
__global__ void count_kernel(const int* __restrict__ dst, int* __restrict__ cnt)
{
    int e = blockIdx.x * blockDim.x + threadIdx.x;
    if (e < EE) atomicAdd(&cnt[dst[e]], 1);
}

__global__ void scan_kernel(const int* __restrict__ cnt, int* __restrict__ rowptr,
                            int* __restrict__ cursor)
{
    __shared__ int sh[2][1024];
    __shared__ int carry_sh;
    int t = threadIdx.x;
    if (t == 0) carry_sh = 0;
    __syncthreads();
    for (int base = 0; base < NN; base += 1024) {
        int i = base + t;
        int v = (i < NN) ? cnt[i] : 0;
        int pin = 0;
        sh[0][t] = v;
        __syncthreads();
        for (int off = 1; off < 1024; off <<= 1) {
            int s = sh[pin][t];
            int add = (t >= off) ? sh[pin][t - off] : 0;
            sh[pin ^ 1][t] = s + add;
            pin ^= 1;
            __syncthreads();
        }
        int incl = sh[pin][t];
        int excl = carry_sh + incl - v;
        if (i < NN) { rowptr[i] = excl; cursor[i] = excl; }
        __syncthreads();
        if (t == 1023) carry_sh += sh[pin][1023];
        __syncthreads();
    }
    if (t == 0) rowptr[NN] = carry_sh;
}

__global__ void fill_kernel(const int* __restrict__ src, const int* __restrict__ dst,
                            int* __restrict__ cursor, int* __restrict__ csrc)
{
    int e = blockIdx.x * blockDim.x + threadIdx.x;
    if (e >= EE) return;
    int d = dst[e];
    int pos = atomicAdd(&cursor[d], 1);
    csrc[pos] = src[e];
}

// ---------------- fused GEMM: C = A @ [W|SW], routed to h / skip --------------
__global__ __launch_bounds__(256) void sgemm_fused(
    const float* __restrict__ A, const float* __restrict__ B,
    const float* __restrict__ sbias, float* __restrict__ hOut, float* __restrict__ skipOut,
    int M, int K, int Npack, int splitH, int splitS)
{
    const int BM = 128, BN = 128, BK = 8, TM = 8, TN = 8;
    __shared__ float As[BK][BM];
    __shared__ float Bs[BK][BN];
    int tid = threadIdx.x;
    int rowBlock = blockIdx.y * BM;
    int colBlock = blockIdx.x * BN;
    int trow = (tid / 16) * TM;
    int tcol = (tid % 16) * TN;
    float acc[TM][TN];
#pragma unroll
    for (int i = 0; i < TM; i++)
#pragma unroll
        for (int j = 0; j < TN; j++) acc[i][j] = 0.f;

    int ar = tid >> 1;            // 0..127
    int ak = (tid & 1) * 4;       // 0 or 4
    int bk = tid >> 5;            // 0..7
    int bc = (tid & 31) * 4;      // 0..124

    for (int k0 = 0; k0 < K; k0 += BK) {
        // A tile (vectorized)
        {
            float4 av = make_float4(0.f, 0.f, 0.f, 0.f);
            int gr = rowBlock + ar, gk = k0 + ak;
            if (gr < M) {
                if (gk + 3 < K) av = *(const float4*)(A + (size_t)gr * K + gk);
                else {
                    if (gk + 0 < K) av.x = A[(size_t)gr * K + gk + 0];
                    if (gk + 1 < K) av.y = A[(size_t)gr * K + gk + 1];
                    if (gk + 2 < K) av.z = A[(size_t)gr * K + gk + 2];
                    if (gk + 3 < K) av.w = A[(size_t)gr * K + gk + 3];
                }
            }
            As[ak + 0][ar] = av.x; As[ak + 1][ar] = av.y;
            As[ak + 2][ar] = av.z; As[ak + 3][ar] = av.w;
        }
        // B tile (vectorized)
        {
            float4 bv = make_float4(0.f, 0.f, 0.f, 0.f);
            int gk = k0 + bk, gc = colBlock + bc;
            if (gk < K) {
                if (gc + 3 < Npack) bv = *(const float4*)(B + (size_t)gk * Npack + gc);
                else {
                    if (gc + 0 < Npack) bv.x = B[(size_t)gk * Npack + gc + 0];
                    if (gc + 1 < Npack) bv.y = B[(size_t)gk * Npack + gc + 1];
                    if (gc + 2 < Npack) bv.z = B[(size_t)gk * Npack + gc + 2];
                    if (gc + 3 < Npack) bv.w = B[(size_t)gk * Npack + gc + 3];
                }
            }
            *(float4*)&Bs[bk][bc] = bv;
        }
        __syncthreads();
#pragma unroll
        for (int kk = 0; kk < BK; kk++) {
            float a[TM], b[TN];
#pragma unroll
            for (int i = 0; i < TM; i++) a[i] = As[kk][trow + i];
#pragma unroll
            for (int j = 0; j < TN; j++) b[j] = Bs[kk][tcol + j];
#pragma unroll
            for (int i = 0; i < TM; i++)
#pragma unroll
                for (int j = 0; j < TN; j++) acc[i][j] = fmaf(a[i], b[j], acc[i][j]);
        }
        __syncthreads();
    }
#pragma unroll
    for (int i = 0; i < TM; i++) {
        int gr = rowBlock + trow + i;
        if (gr >= M) continue;
#pragma unroll
        for (int j = 0; j < TN; j++) {
            int gc = colBlock + tcol + j;
            float v = acc[i][j];
            if (gc < splitH) {
                hOut[(size_t)gr * splitH + gc] = v;
            } else if (gc < splitH + splitS) {
                int sc = gc - splitH;
                skipOut[(size_t)gr * splitS + sc] = v + sbias[sc];
            }
        }
    }
}

// ---------------- per-(node,head) attention logits ----------------
__global__ void al_kernel(const float* __restrict__ h, const float* __restrict__ a_s,
                          const float* __restrict__ a_d, float* __restrict__ als,
                          float* __restrict__ ald, int C)
{
    int w = (blockIdx.x * blockDim.x + threadIdx.x) >> 5;
    int lane = threadIdx.x & 31;
    if (w >= NN * HEADS) return;
    int n = w >> 2, hd = w & 3;
    const float* hp = h + (size_t)n * (HEADS * C) + hd * C;
    float ss = 0.f, sd = 0.f;
    for (int c = lane; c < C; c += 32) {
        float v = hp[c];
        ss = fmaf(v, a_s[hd * C + c], ss);
        sd = fmaf(v, a_d[hd * C + c], sd);
    }
#pragma unroll
    for (int o = 16; o; o >>= 1) {
        ss += __shfl_xor_sync(0xffffffffu, ss, o);
        sd += __shfl_xor_sync(0xffffffffu, sd, o);
    }
    if (lane == 0) { als[w] = ss; ald[w] = sd; }
}

// ---------------- fused GAT aggregation (layers 0/1): warp per dst node ------
// out = (sum_e e_h * h[src]) / (sum_e e_h) + bias + skip   (no atomics)
__global__ __launch_bounds__(256) void gat_agg_kernel(
    const int* __restrict__ rowptr, const int* __restrict__ csrc,
    const float* __restrict__ h, const float* __restrict__ als,
    const float* __restrict__ ald, const float* __restrict__ bias,
    const float* __restrict__ skip, float* __restrict__ outp)
{
    int w = (blockIdx.x * blockDim.x + threadIdx.x) >> 5;
    int lane = threadIdx.x & 31;
    if (w >= NN) return;
    int head = lane >> 3;                  // 8 channels per lane -> head = lane/8
    float ad = ald[w * 4 + head];
    int beg = rowptr[w], end = rowptr[w + 1];
    float4 acc0 = make_float4(0.f, 0.f, 0.f, 0.f);
    float4 acc1 = make_float4(0.f, 0.f, 0.f, 0.f);
    float den = 0.f;
    int s_next = (beg < end) ? csrc[beg] : 0;
    for (int i = beg; i < end; i++) {
        int s = s_next;
        if (i + 1 < end) s_next = csrc[i + 1];
        float e = expf(lrelu(als[s * 4 + head] + ad));
        den += e;
        const float4* hp = reinterpret_cast<const float4*>(h + (size_t)s * HC) + lane * 2;
        float4 v0 = hp[0], v1 = hp[1];
        acc0.x = fmaf(e, v0.x, acc0.x); acc0.y = fmaf(e, v0.y, acc0.y);
        acc0.z = fmaf(e, v0.z, acc0.z); acc0.w = fmaf(e, v0.w, acc0.w);
        acc1.x = fmaf(e, v1.x, acc1.x); acc1.y = fmaf(e, v1.y, acc1.y);
        acc1.z = fmaf(e, v1.z, acc1.z); acc1.w = fmaf(e, v1.w, acc1.w);
    }
    float inv = 1.f / (den + 1e-16f);
    int cbase = lane * 8;
    size_t obase = (size_t)w * HC + cbase;
    const float4* bp = reinterpret_cast<const float4*>(bias + cbase);
    const float4* sp = reinterpret_cast<const float4*>(skip + obase);
    float4 b0 = bp[0], b1 = bp[1];
    float4 s0 = sp[0], s1 = sp[1];
    float4 o0, o1;
    o0.x = fmaf(acc0.x, inv, b0.x + s0.x); o0.y = fmaf(acc0.y, inv, b0.y + s0.y);
    o0.z = fmaf(acc0.z, inv, b0.z + s0.z); o0.w = fmaf(acc0.w, inv, b0.w + s0.w);
    o1.x = fmaf(acc1.x, inv, b1.x + s1.x); o1.y = fmaf(acc1.y, inv, b1.y + s1.y);
    o1.z = fmaf(acc1.z, inv, b1.z + s1.z); o1.w = fmaf(acc1.w, inv, b1.w + s1.w);
    float4* op = reinterpret_cast<float4*>(outp + obase);
    op[0] = o0; op[1] = o1;
}

// ---------------- layer 2: agg (mean over heads) + bias + skip + log_softmax -
__global__ __launch_bounds__(256) void gat_agg47_fused(
    const int* __restrict__ rowptr, const int* __restrict__ csrc,
    const float* __restrict__ h, const float4* __restrict__ als,
    const float4* __restrict__ ald, const float* __restrict__ b2,
    const float* __restrict__ skip47, float* __restrict__ outp)
{
    int w = (blockIdx.x * blockDim.x + threadIdx.x) >> 5;
    int lane = threadIdx.x & 31;
    if (w >= NN) return;
    float4 ad = ald[w];
    int beg = rowptr[w], end = rowptr[w + 1];
    float a0 = 0.f, a1 = 0.f, a2 = 0.f, a3 = 0.f;      // c = lane
    float c0 = 0.f, c1 = 0.f, c2 = 0.f, c3 = 0.f;      // c = lane+32
    float d0 = 0.f, d1 = 0.f, d2 = 0.f, d3 = 0.f;
    bool has2 = (lane + 32) < NCLS;
    int s_next = (beg < end) ? csrc[beg] : 0;
    for (int i = beg; i < end; i++) {
        int s = s_next;
        if (i + 1 < end) s_next = csrc[i + 1];
        float4 as4 = als[s];
        float e0 = expf(lrelu(as4.x + ad.x));
        float e1 = expf(lrelu(as4.y + ad.y));
        float e2 = expf(lrelu(as4.z + ad.z));
        float e3 = expf(lrelu(as4.w + ad.w));
        d0 += e0; d1 += e1; d2 += e2; d3 += e3;
        const float* hs = h + (size_t)s * L2OUT;
        a0 = fmaf(e0, hs[lane], a0);
        a1 = fmaf(e1, hs[NCLS + lane], a1);
        a2 = fmaf(e2, hs[2 * NCLS + lane], a2);
        a3 = fmaf(e3, hs[3 * NCLS + lane], a3);
        if (has2) {
            int c = lane + 32;
            c0 = fmaf(e0, hs[c], c0);
            c1 = fmaf(e1, hs[NCLS + c], c1);
            c2 = fmaf(e2, hs[2 * NCLS + c], c2);
            c3 = fmaf(e3, hs[3 * NCLS + c], c3);
        }
    }
    float i0 = 1.f / (d0 + 1e-16f), i1 = 1.f / (d1 + 1e-16f);
    float i2 = 1.f / (d2 + 1e-16f), i3 = 1.f / (d3 + 1e-16f);
    float v0 = 0.25f * (a0 * i0 + a1 * i1 + a2 * i2 + a3 * i3)
             + b2[lane] + skip47[(size_t)w * NCLS + lane];
    float v1 = -1e30f;
    if (has2) {
        int c = lane + 32;
        v1 = 0.25f * (c0 * i0 + c1 * i1 + c2 * i2 + c3 * i3)
           + b2[c] + skip47[(size_t)w * NCLS + c];
    }
    float m = fmaxf(v0, v1);
#pragma unroll
    for (int o = 16; o; o >>= 1) m = fmaxf(m, __shfl_xor_sync(0xffffffffu, m, o));
    float s = expf(v0 - m) + (has2 ? expf(v1 - m) : 0.f);
#pragma unroll
    for (int o = 16; o; o >>= 1) s += __shfl_xor_sync(0xffffffffu, s, o);
    float lse = m + logf(s);
    outp[(size_t)w * NCLS + lane] = v0 - lse;
    if (has2) outp[(size_t)w * NCLS + lane + 32] = v1 - lse;
}

// ---------------- BN stats (read-only): accumulate sum & sumsq ---------------
__global__ void bn_stats_kernel(const float* __restrict__ pre, float* __restrict__ sums)
{
    int c = threadIdx.x;           // 256 channels
    float s = 0.f, s2 = 0.f;
    for (int r = blockIdx.x; r < NN; r += gridDim.x) {
        float v = pre[(size_t)r * HC + c];
        s += v;
        s2 = fmaf(v, v, s2);
    }
    atomicAdd(&sums[c], s);
    atomicAdd(&sums[HC + c], s2);
}

// ---------------- BN apply + ELU ----------------
__global__ void bn_apply_kernel(const float* __restrict__ pre, const float* __restrict__ sums,
                                const float* __restrict__ gamma, const float* __restrict__ beta,
                                float* __restrict__ outp)
{
    int c = threadIdx.x;
    float mu = sums[c] * (1.f / NN);
    float var = sums[HC + c] * (1.f / NN) - mu * mu;
    float rstd = rsqrtf(var + 1e-5f);
    float g = gamma[c] * rstd;
    float b = beta[c] - mu * g;
    for (int r = blockIdx.x; r < NN; r += gridDim.x) {
        size_t idx = (size_t)r * HC + c;
        float v = fmaf(pre[idx], g, b);
        outp[idx] = v > 0.f ? v : expf(v) - 1.f;
    }
}

// ---------------- host orchestration ----------------
extern "C" void kernel_launch(void* const* d_in, const int* in_sizes, int n_in,
                              void* d_out, int out_size)
{
    const float* x   = (const float*)d_in[0];
    const int*   ei  = (const int*)d_in[1];
    const float* w0  = (const float*)d_in[2];
    const float* as0 = (const float*)d_in[3];
    const float* ad0 = (const float*)d_in[4];
    const float* b0  = (const float*)d_in[5];
    const float* sw0 = (const float*)d_in[6];
    const float* sb0 = (const float*)d_in[7];
    const float* g0  = (const float*)d_in[8];
    const float* be0 = (const float*)d_in[9];
    const float* w1  = (const float*)d_in[10];
    const float* as1 = (const float*)d_in[11];
    const float* ad1 = (const float*)d_in[12];
    const float* b1  = (const float*)d_in[13];
    const float* sw1 = (const float*)d_in[14];
    const float* sb1 = (const float*)d_in[15];
    const float* g1  = (const float*)d_in[16];
    const float* be1 = (const float*)d_in[17];
    const float* w2  = (const float*)d_in[18];
    const float* as2 = (const float*)d_in[19];
    const float* ad2 = (const float*)d_in[20];
    const float* b2  = (const float*)d_in[21];
    const float* sw2 = (const float*)d_in[22];
    const float* sb2 = (const float*)d_in[23];

    const int* src = ei;
    const int* dst = ei + EE;

    float *h, *skip, *agg, *hcur, *als, *ald, *bnsum, *p0, *p1, *p2;
    int *cnt, *rowptr, *cursor, *csrc;
    cudaGetSymbolAddress((void**)&h, g_h);
    cudaGetSymbolAddress((void**)&skip, g_skip);
    cudaGetSymbolAddress((void**)&agg, g_agg);
    cudaGetSymbolAddress((void**)&hcur, g_hcur);
    cudaGetSymbolAddress((void**)&als, g_als);
    cudaGetSymbolAddress((void**)&ald, g_ald);
    cudaGetSymbolAddress((void**)&bnsum, g_bnsum);
    cudaGetSymbolAddress((void**)&p0, g_p0);
    cudaGetSymbolAddress((void**)&p1, g_p1);
    cudaGetSymbolAddress((void**)&p2, g_p2);
    cudaGetSymbolAddress((void**)&cnt, g_cnt);
    cudaGetSymbolAddress((void**)&rowptr, g_rowptr);
    cudaGetSymbolAddress((void**)&cursor, g_cursor);
    cudaGetSymbolAddress((void**)&csrc, g_csrc);

    dim3 gemm512(4, (NN + 127) / 128);
    dim3 gemm240(2, (NN + 127) / 128);
    int alBlocks = (NN * HEADS * 32 + 255) / 256;
    int nodeWarpBlocks = (NN * 32 + 255) / 256;
    int eBlocks = (EE + 255) / 256;

    // ===== CSR build (reused by all 3 layers) =====
    cudaMemsetAsync(cnt, 0, NN * sizeof(int));
    count_kernel<<<eBlocks, 256>>>(dst, cnt);
    scan_kernel<<<1, 1024>>>(cnt, rowptr, cursor);
    fill_kernel<<<eBlocks, 256>>>(src, dst, cursor, csrc);

    // ===== pack weights =====
    pack_weights<<<480, 256>>>(w0, sw0, w1, sw1, w2, sw2, p0, p1, p2);

    // ===== Layer 0 =====
    sgemm_fused<<<gemm512, 256>>>(x, p0, sb0, h, skip, NN, F_IN, 512, HC, HC);
    al_kernel<<<alBlocks, 256>>>(h, as0, ad0, als, ald, HID);
    gat_agg_kernel<<<nodeWarpBlocks, 256>>>(rowptr, csrc, h, als, ald, b0, skip, agg);
    cudaMemsetAsync(bnsum, 0, 2 * HC * sizeof(float));
    bn_stats_kernel<<<512, 256>>>(agg, bnsum);
    bn_apply_kernel<<<512, 256>>>(agg, bnsum, g0, be0, hcur);

    // ===== Layer 1 =====
    sgemm_fused<<<gemm512, 256>>>(hcur, p1, sb1, h, skip, NN, HC, 512, HC, HC);
    al_kernel<<<alBlocks, 256>>>(h, as1, ad1, als, ald, HID);
    gat_agg_kernel<<<nodeWarpBlocks, 256>>>(rowptr, csrc, h, als, ald, b1, skip, agg);
    cudaMemsetAsync(bnsum, 0, 2 * HC * sizeof(float));
    bn_stats_kernel<<<512, 256>>>(agg, bnsum);
    bn_apply_kernel<<<512, 256>>>(agg, bnsum, g1, be1, hcur);

    // ===== Layer 2 =====
    sgemm_fused<<<gemm240, 256>>>(hcur, p2, sb2, h, skip, NN, HC, NP2, L2OUT, NCLS);
    al_kernel<<<alBlocks, 256>>>(h, as2, ad2, als, ald, NCLS);
    gat_agg47_fused<<<nodeWarpBlocks, 256>>>(rowptr, csrc, h, (const float4*)als,
                                             (const float4*)ald, b2, skip, (float*)d_out);
}

// round 3
// speedup vs baseline: 2.3263x; 1.4904x over previous
#include <cuda_runtime.h>
#include <cuda_bf16.h>
#include <cuda_fp16.h>
#include <math.h>

#define NN 30000
#define EE 480000
#define F_IN 100
#define HID 64
#define HEADS 4
#define NCLS 47
#define HC 256           // HEADS*HID
#define L2OUT 188        // HEADS*NCLS
#define NP2 240          // padded pack width for layer 2 (188+47 -> 240)
#define NBLK 118         // ceil(NN/256) for scan

// ---------------- scratch (device globals; no allocs allowed) ----------------
__device__ __align__(16) float g_h[(size_t)NN * HC];
__device__ __align__(16) float g_skip[(size_t)NN * HC];
__device__ __align__(16) float g_agg[(size_t)NN * HC];
__device__ __align__(16) float g_hcur[(size_t)NN * HC];
__device__ __align__(16) float g_als[(size_t)NN * HEADS];
__device__ __align__(16) float g_ald[(size_t)NN * HEADS];
__device__ float g_bnsum[2 * HC];
// CSR
__device__ int g_cnt[NN];
__device__ int g_part[NN];
__device__ int g_bsum[NBLK];
__device__ int g_rowptr[NN + 1];
__device__ int g_cursor[NN];
__device__ int g_csrc[EE];
// packed weights
__device__ __align__(16) float g_p0[F_IN * 512];
__device__ __align__(16) float g_p1[HC * 512];
__device__ __align__(16) float g_p2[HC * NP2];

__device__ __forceinline__ float lrelu(float x) { return x > 0.f ? x : 0.2f * x; }

// ---------------- pack [W | SW] per layer ----------------
__global__ void pack_weights(const float* __restrict__ w0, const float* __restrict__ sw0,
                             const float* __restrict__ w1, const float* __restrict__ sw1,
                             const float* __restrict__ w2, const float* __restrict__ sw2,
                             float* __restrict__ p0, float* __restrict__ p1, float* __restrict__ p2)
{
    int tid = blockIdx.x * blockDim.x + threadIdx.x;
    int stride = gridDim.x * blockDim.x;
    for (int i = tid; i < F_IN * 512; i += stride) {
        int k = i / 512, c = i % 512;
        p0[i] = (c < HC) ? w0[k * HC + c] : sw0[k * HC + (c - HC)];
    }
    for (int i = tid; i < HC * 512; i += stride) {
        int k = i / 512, c = i % 512;
        p1[i] = (c < HC) ? w1[k * HC + c] : sw1[k * HC + (c - HC)];
    }
    for (int i = tid; i < HC * NP2; i += stride) {
        int k = i / NP2, c = i % NP2;
        float v = 0.f;
        if (c < L2OUT) v = w2[k * L2OUT + c];
        else if (c < L2OUT + NCLS) v = sw2[k * NCLS + (c - L2OUT)];
        p2[i] = v;
    }
}

// ---------------- CSR build ----------------
__global__ void count_kernel(const int* __restrict__ dst, int* __restrict__ cnt)
{
    int e = blockIdx.x * blockDim.x + threadIdx.x;
    if (e < EE) atomicAdd(&cnt[dst[e]], 1);
}

__global__ void scan_blocks(const int* __restrict__ cnt, int* __restrict__ part,
                            int* __restrict__ bsum)
{
    int t = threadIdx.x;
    int i = blockIdx.x * 256 + t;
    int lane = t & 31, wid = t >> 5;
    int v = (i < NN) ? cnt[i] : 0;
    int x = v;
#pragma unroll
    for (int off = 1; off < 32; off <<= 1) {
        int y = __shfl_up_sync(0xffffffffu, x, off);
        if (lane >= off) x += y;
    }
    __shared__ int wsum[8];
    if (lane == 31) wsum[wid] = x;
    __syncthreads();
    if (wid == 0 && lane < 8) {
        int w = wsum[lane];
#pragma unroll
        for (int off = 1; off < 8; off <<= 1) {
            int y = __shfl_up_sync(0xffu, w, off);
            if (lane >= off) w += y;
        }
        wsum[lane] = w;
    }
    __syncthreads();
    int base = (wid > 0) ? wsum[wid - 1] : 0;
    int incl = x + base;
    if (i < NN) part[i] = incl - v;
    if (t == 255) bsum[blockIdx.x] = incl;
}

__global__ void scan_totals(int* __restrict__ bsum)
{
    int t = threadIdx.x;       // 128 threads, NBLK=118 entries
    int lane = t & 31, wid = t >> 5;
    int v = (t < NBLK) ? bsum[t] : 0;
    int x = v;
#pragma unroll
    for (int off = 1; off < 32; off <<= 1) {
        int y = __shfl_up_sync(0xffffffffu, x, off);
        if (lane >= off) x += y;
    }
    __shared__ int wsum[4];
    if (lane == 31) wsum[wid] = x;
    __syncthreads();
    if (wid == 0 && lane < 4) {
        int w = wsum[lane];
#pragma unroll
        for (int off = 1; off < 4; off <<= 1) {
            int y = __shfl_up_sync(0xfu, w, off);
            if (lane >= off) w += y;
        }
        wsum[lane] = w;
    }
    __syncthreads();
    int base = (wid > 0) ? wsum[wid - 1] : 0;
    if (t < NBLK) bsum[t] = x + base - v;   // exclusive
}

__global__ void scan_add(const int* __restrict__ part, const int* __restrict__ bsum,
                         int* __restrict__ rowptr, int* __restrict__ cursor)
{
    int i = blockIdx.x * 256 + threadIdx.x;
    if (i < NN) {
        int r = part[i] + bsum[i >> 8];
        rowptr[i] = r;
        cursor[i] = r;
    }
    if (i == NN) rowptr[NN] = EE;
}

__global__ void fill_kernel(const int* __restrict__ src, const int* __restrict__ dst,
                            int* __restrict__ cursor, int* __restrict__ csrc)
{
    int e = blockIdx.x * blockDim.x + threadIdx.x;
    if (e >= EE) return;
    int d = dst[e];
    int pos = atomicAdd(&cursor[d], 1);
    csrc[pos] = src[e];
}

// ---------------- tensor-core GEMM (fp16 hi/lo split, fp32 accumulate) -------
// C = A[M,K] @ B[K,Npack]; columns [0,splitH) -> hOut, [splitH, splitH+splitS) -> skipOut+sbias
#define BM 128
#define BN 128
#define BKK 32
#define BKP 34

__device__ __forceinline__ void mma16816(float* d, const unsigned* a, const unsigned* b)
{
    asm volatile(
        "mma.sync.aligned.m16n8k16.row.col.f32.f16.f16.f32 "
        "{%0,%1,%2,%3}, {%4,%5,%6,%7}, {%8,%9}, {%0,%1,%2,%3};"
        : "+f"(d[0]), "+f"(d[1]), "+f"(d[2]), "+f"(d[3])
        : "r"(a[0]), "r"(a[1]), "r"(a[2]), "r"(a[3]), "r"(b[0]), "r"(b[1]));
}

__global__ __launch_bounds__(256, 1) void hgemm_split(
    const float* __restrict__ A, const float* __restrict__ B,
    const float* __restrict__ sbias, float* __restrict__ hOut, float* __restrict__ skipOut,
    int M, int K, int Npack, int splitH, int splitS)
{
    __shared__ __align__(16) __half As[2][BM * BKP];
    __shared__ __align__(16) __half Bs[2][BN * BKP];

    int tid = threadIdx.x;
    int lane = tid & 31, wid = tid >> 5;
    int rowBlock = blockIdx.y * BM;
    int colBlock = blockIdx.x * BN;
    int wm = (wid & 1) * 64;    // warp row base within tile
    int wn = (wid >> 1) * 32;   // warp col base within tile
    int gID = lane >> 2, tig = lane & 3;

    float acc[4][4][4];
#pragma unroll
    for (int mt = 0; mt < 4; mt++)
#pragma unroll
        for (int nt = 0; nt < 4; nt++)
#pragma unroll
            for (int r = 0; r < 4; r++) acc[mt][nt][r] = 0.f;

    int kIters = (K + BKK - 1) / BKK;

    float4 aR[4], bR[4];
    // prefetch iter 0
    {
        int k0 = 0;
#pragma unroll
        for (int i = 0; i < 4; i++) {
            int lin = tid + i * 256;
            int m = lin >> 3, k = (lin & 7) * 4;
            int gr = rowBlock + m, gk = k0 + k;
            float4 v = make_float4(0.f, 0.f, 0.f, 0.f);
            if (gr < M && gk < K) v = *(const float4*)(A + (size_t)gr * K + gk);
            aR[i] = v;
        }
#pragma unroll
        for (int i = 0; i < 4; i++) {
            int lin = tid + i * 256;
            int kk = lin >> 5, n = (lin & 31) * 4;
            int gk = k0 + kk, gc = colBlock + n;
            float4 v = make_float4(0.f, 0.f, 0.f, 0.f);
            if (gk < K && gc < Npack) v = *(const float4*)(B + (size_t)gk * Npack + gc);
            bR[i] = v;
        }
    }

    for (int it = 0; it < kIters; it++) {
        // stage regs -> smem (fp32 -> hi/lo half)
#pragma unroll
        for (int i = 0; i < 4; i++) {
            int lin = tid + i * 256;
            int m = lin >> 3, k = (lin & 7) * 4;
            float vv[4] = {aR[i].x, aR[i].y, aR[i].z, aR[i].w};
#pragma unroll
            for (int j = 0; j < 4; j++) {
                float v = vv[j];
                __half hi = __float2half_rn(v);
                __half lo = __float2half_rn(v - __half2float(hi));
                As[0][m * BKP + k + j] = hi;
                As[1][m * BKP + k + j] = lo;
            }
        }
#pragma unroll
        for (int i = 0; i < 4; i++) {
            int lin = tid + i * 256;
            int kk = lin >> 5, n = (lin & 31) * 4;
            float vv[4] = {bR[i].x, bR[i].y, bR[i].z, bR[i].w};
#pragma unroll
            for (int j = 0; j < 4; j++) {
                float v = vv[j];
                __half hi = __float2half_rn(v);
                __half lo = __float2half_rn(v - __half2float(hi));
                Bs[0][(n + j) * BKP + kk] = hi;
                Bs[1][(n + j) * BKP + kk] = lo;
            }
        }
        __syncthreads();

        // prefetch next iter
        int k0n = (it + 1) * BKK;
        if (it + 1 < kIters) {
#pragma unroll
            for (int i = 0; i < 4; i++) {
                int lin = tid + i * 256;
                int m = lin >> 3, k = (lin & 7) * 4;
                int gr = rowBlock + m, gk = k0n + k;
                float4 v = make_float4(0.f, 0.f, 0.f, 0.f);
                if (gr < M && gk < K) v = *(const float4*)(A + (size_t)gr * K + gk);
                aR[i] = v;
            }
#pragma unroll
            for (int i = 0; i < 4; i++) {
                int lin = tid + i * 256;
                int kk = lin >> 5, n = (lin & 31) * 4;
                int gk = k0n + kk, gc = colBlock + n;
                float4 v = make_float4(0.f, 0.f, 0.f, 0.f);
                if (gk < K && gc < Npack) v = *(const float4*)(B + (size_t)gk * Npack + gc);
                bR[i] = v;
            }
        }

        // compute 2 k-steps of 16
#pragma unroll
        for (int ks = 0; ks < 2; ks++) {
            int kk = ks * 16;
            unsigned aH[4][4], aL[4][4];
#pragma unroll
            for (int mt = 0; mt < 4; mt++) {
                int r0 = wm + mt * 16 + gID;
                int r1 = r0 + 8;
                int c0 = kk + tig * 2;
                int c1 = c0 + 8;
                aH[mt][0] = *(const unsigned*)&As[0][r0 * BKP + c0];
                aH[mt][1] = *(const unsigned*)&As[0][r1 * BKP + c0];
                aH[mt][2] = *(const unsigned*)&As[0][r0 * BKP + c1];
                aH[mt][3] = *(const unsigned*)&As[0][r1 * BKP + c1];
                aL[mt][0] = *(const unsigned*)&As[1][r0 * BKP + c0];
                aL[mt][1] = *(const unsigned*)&As[1][r1 * BKP + c0];
                aL[mt][2] = *(const unsigned*)&As[1][r0 * BKP + c1];
                aL[mt][3] = *(const unsigned*)&As[1][r1 * BKP + c1];
            }
            unsigned bH[4][2], bL[4][2];
#pragma unroll
            for (int nt = 0; nt < 4; nt++) {
                int n = wn + nt * 8 + gID;
                int c0 = kk + tig * 2;
                bH[nt][0] = *(const unsigned*)&Bs[0][n * BKP + c0];
                bH[nt][1] = *(const unsigned*)&Bs[0][n * BKP + c0 + 8];
                bL[nt][0] = *(const unsigned*)&Bs[1][n * BKP + c0];
                bL[nt][1] = *(const unsigned*)&Bs[1][n * BKP + c0 + 8];
            }
#pragma unroll
            for (int mt = 0; mt < 4; mt++)
#pragma unroll
                for (int nt = 0; nt < 4; nt++) {
                    mma16816(acc[mt][nt], aH[mt], bH[nt]);
                    mma16816(acc[mt][nt], aH[mt], bL[nt]);
                    mma16816(acc[mt][nt], aL[mt], bH[nt]);
                }
        }
        __syncthreads();
    }

    // epilogue: route to hOut / skipOut(+sbias)
#pragma unroll
    for (int mt = 0; mt < 4; mt++) {
        int gr0 = rowBlock + wm + mt * 16 + gID;
        int gr1 = gr0 + 8;
#pragma unroll
        for (int nt = 0; nt < 4; nt++) {
            int gc = colBlock + wn + nt * 8 + tig * 2;
#pragma unroll
            for (int half_ = 0; half_ < 2; half_++) {
                int gr = half_ ? gr1 : gr0;
                if (gr >= M) continue;
                float v0 = acc[mt][nt][half_ * 2 + 0];
                float v1 = acc[mt][nt][half_ * 2 + 1];
#pragma unroll
                for (int j = 0; j < 2; j++) {
                    int c = gc + j;
                    float v = j ? v1 : v0;
                    if (c < splitH) {
                        hOut[(size_t)gr * splitH + c] = v;
                    } else if (c < splitH + splitS) {
                        int sc = c - splitH;
                        skipOut[(size_t)gr * splitS + sc] = v + sbias[sc];
                    }
                }
            }
        }
    }
}

// ---------------- per-(node,head) attention logits ----------------
__global__ void al_kernel(const float* __restrict__ h, const float* __restrict__ a_s,
                          const float* __restrict__ a_d, float* __restrict__ als,
                          float* __restrict__ ald, int C)
{
    int w = (blockIdx.x * blockDim.x + threadIdx.x) >> 5;
    int lane = threadIdx.x & 31;
    if (w >= NN * HEADS) return;
    int n = w >> 2, hd = w & 3;
    const float* hp = h + (size_t)n * (HEADS * C) + hd * C;
    float ss = 0.f, sd = 0.f;
    for (int c = lane; c < C; c += 32) {
        float v = hp[c];
        ss = fmaf(v, a_s[hd * C + c], ss);
        sd = fmaf(v, a_d[hd * C + c], sd);
    }
#pragma unroll
    for (int o = 16; o; o >>= 1) {
        ss += __shfl_xor_sync(0xffffffffu, ss, o);
        sd += __shfl_xor_sync(0xffffffffu, sd, o);
    }
    if (lane == 0) { als[w] = ss; ald[w] = sd; }
}

// ---------------- fused GAT aggregation (layers 0/1): warp per dst node ------
__global__ __launch_bounds__(256) void gat_agg_kernel(
    const int* __restrict__ rowptr, const int* __restrict__ csrc,
    const float* __restrict__ h, const float* __restrict__ als,
    const float* __restrict__ ald, const float* __restrict__ bias,
    const float* __restrict__ skip, float* __restrict__ outp)
{
    int w = (blockIdx.x * blockDim.x + threadIdx.x) >> 5;
    int lane = threadIdx.x & 31;
    if (w >= NN) return;
    int head = lane >> 3;
    float ad = ald[w * 4 + head];
    int beg = rowptr[w], end = rowptr[w + 1];
    float4 acc0 = make_float4(0.f, 0.f, 0.f, 0.f);
    float4 acc1 = make_float4(0.f, 0.f, 0.f, 0.f);
    float den = 0.f;
    int s_next = (beg < end) ? csrc[beg] : 0;
    for (int i = beg; i < end; i++) {
        int s = s_next;
        if (i + 1 < end) s_next = csrc[i + 1];
        float e = expf(lrelu(als[s * 4 + head] + ad));
        den += e;
        const float4* hp = reinterpret_cast<const float4*>(h + (size_t)s * HC) + lane * 2;
        float4 v0 = hp[0], v1 = hp[1];
        acc0.x = fmaf(e, v0.x, acc0.x); acc0.y = fmaf(e, v0.y, acc0.y);
        acc0.z = fmaf(e, v0.z, acc0.z); acc0.w = fmaf(e, v0.w, acc0.w);
        acc1.x = fmaf(e, v1.x, acc1.x); acc1.y = fmaf(e, v1.y, acc1.y);
        acc1.z = fmaf(e, v1.z, acc1.z); acc1.w = fmaf(e, v1.w, acc1.w);
    }
    float inv = 1.f / (den + 1e-16f);
    int cbase = lane * 8;
    size_t obase = (size_t)w * HC + cbase;
    const float4* bp = reinterpret_cast<const float4*>(bias + cbase);
    const float4* sp = reinterpret_cast<const float4*>(skip + obase);
    float4 b0 = bp[0], b1 = bp[1];
    float4 s0 = sp[0], s1 = sp[1];
    float4 o0, o1;
    o0.x = fmaf(acc0.x, inv, b0.x + s0.x); o0.y = fmaf(acc0.y, inv, b0.y + s0.y);
    o0.z = fmaf(acc0.z, inv, b0.z + s0.z); o0.w = fmaf(acc0.w, inv, b0.w + s0.w);
    o1.x = fmaf(acc1.x, inv, b1.x + s1.x); o1.y = fmaf(acc1.y, inv, b1.y + s1.y);
    o1.z = fmaf(acc1.z, inv, b1.z + s1.z); o1.w = fmaf(acc1.w, inv, b1.w + s1.w);
    float4* op = reinterpret_cast<float4*>(outp + obase);
    op[0] = o0; op[1] = o1;
}

// ---------------- layer 2: agg (mean over heads) + bias + skip + log_softmax -
__global__ __launch_bounds__(256) void gat_agg47_fused(
    const int* __restrict__ rowptr, const int* __restrict__ csrc,
    const float* __restrict__ h, const float4* __restrict__ als,
    const float4* __restrict__ ald, const float* __restrict__ b2,
    const float* __restrict__ skip47, float* __restrict__ outp)
{
    int w = (blockIdx.x * blockDim.x + threadIdx.x) >> 5;
    int lane = threadIdx.x & 31;
    if (w >= NN) return;
    float4 ad = ald[w];
    int beg = rowptr[w], end = rowptr[w + 1];
    float a0 = 0.f, a1 = 0.f, a2 = 0.f, a3 = 0.f;
    float c0 = 0.f, c1 = 0.f, c2 = 0.f, c3 = 0.f;
    float d0 = 0.f, d1 = 0.f, d2 = 0.f, d3 = 0.f;
    bool has2 = (lane + 32) < NCLS;
    int s_next = (beg < end) ? csrc[beg] : 0;
    for (int i = beg; i < end; i++) {
        int s = s_next;
        if (i + 1 < end) s_next = csrc[i + 1];
        float4 as4 = als[s];
        float e0 = expf(lrelu(as4.x + ad.x));
        float e1 = expf(lrelu(as4.y + ad.y));
        float e2 = expf(lrelu(as4.z + ad.z));
        float e3 = expf(lrelu(as4.w + ad.w));
        d0 += e0; d1 += e1; d2 += e2; d3 += e3;
        const float* hs = h + (size_t)s * L2OUT;
        a0 = fmaf(e0, hs[lane], a0);
        a1 = fmaf(e1, hs[NCLS + lane], a1);
        a2 = fmaf(e2, hs[2 * NCLS + lane], a2);
        a3 = fmaf(e3, hs[3 * NCLS + lane], a3);
        if (has2) {
            int c = lane + 32;
            c0 = fmaf(e0, hs[c], c0);
            c1 = fmaf(e1, hs[NCLS + c], c1);
            c2 = fmaf(e2, hs[2 * NCLS + c], c2);
            c3 = fmaf(e3, hs[3 * NCLS + c], c3);
        }
    }
    float i0 = 1.f / (d0 + 1e-16f), i1 = 1.f / (d1 + 1e-16f);
    float i2 = 1.f / (d2 + 1e-16f), i3 = 1.f / (d3 + 1e-16f);
    float v0 = 0.25f * (a0 * i0 + a1 * i1 + a2 * i2 + a3 * i3)
             + b2[lane] + skip47[(size_t)w * NCLS + lane];
    float v1 = -1e30f;
    if (has2) {
        int c = lane + 32;
        v1 = 0.25f * (c0 * i0 + c1 * i1 + c2 * i2 + c3 * i3)
           + b2[c] + skip47[(size_t)w * NCLS + c];
    }
    float m = fmaxf(v0, v1);
#pragma unroll
    for (int o = 16; o; o >>= 1) m = fmaxf(m, __shfl_xor_sync(0xffffffffu, m, o));
    float s = expf(v0 - m) + (has2 ? expf(v1 - m) : 0.f);
#pragma unroll
    for (int o = 16; o; o >>= 1) s += __shfl_xor_sync(0xffffffffu, s, o);
    float lse = m + logf(s);
    outp[(size_t)w * NCLS + lane] = v0 - lse;
    if (has2) outp[(size_t)w * NCLS + lane + 32] = v1 - lse;
}

// ---------------- BN stats ----------------
__global__ void bn_stats_kernel(const float* __restrict__ pre, float* __restrict__ sums)
{
    int c = threadIdx.x;
    float s = 0.f, s2 = 0.f;
    for (int r = blockIdx.x; r < NN; r += gridDim.x) {
        float v = pre[(size_t)r * HC + c];
        s += v;
        s2 = fmaf(v, v, s2);
    }
    atomicAdd(&sums[c], s);
    atomicAdd(&sums[HC + c], s2);
}

// ---------------- BN apply + ELU ----------------
__global__ void bn_apply_kernel(const float* __restrict__ pre, const float* __restrict__ sums,
                                const float* __restrict__ gamma, const float* __restrict__ beta,
                                float* __restrict__ outp)
{
    int c = threadIdx.x;
    float mu = sums[c] * (1.f / NN);
    float var = sums[HC + c] * (1.f / NN) - mu * mu;
    float rstd = rsqrtf(var + 1e-5f);
    float g = gamma[c] * rstd;
    float b = beta[c] - mu * g;
    for (int r = blockIdx.x; r < NN; r += gridDim.x) {
        size_t idx = (size_t)r * HC + c;
        float v = fmaf(pre[idx], g, b);
        outp[idx] = v > 0.f ? v : expf(v) - 1.f;
    }
}

// ---------------- host orchestration ----------------
extern "C" void kernel_launch(void* const* d_in, const int* in_sizes, int n_in,
                              void* d_out, int out_size)
{
    const float* x   = (const float*)d_in[0];
    const int*   ei  = (const int*)d_in[1];
    const float* w0  = (const float*)d_in[2];
    const float* as0 = (const float*)d_in[3];
    const float* ad0 = (const float*)d_in[4];
    const float* b0  = (const float*)d_in[5];
    const float* sw0 = (const float*)d_in[6];
    const float* sb0 = (const float*)d_in[7];
    const float* g0  = (const float*)d_in[8];
    const float* be0 = (const float*)d_in[9];
    const float* w1  = (const float*)d_in[10];
    const float* as1 = (const float*)d_in[11];
    const float* ad1 = (const float*)d_in[12];
    const float* b1  = (const float*)d_in[13];
    const float* sw1 = (const float*)d_in[14];
    const float* sb1 = (const float*)d_in[15];
    const float* g1  = (const float*)d_in[16];
    const float* be1 = (const float*)d_in[17];
    const float* w2  = (const float*)d_in[18];
    const float* as2 = (const float*)d_in[19];
    const float* ad2 = (const float*)d_in[20];
    const float* b2  = (const float*)d_in[21];
    const float* sw2 = (const float*)d_in[22];
    const float* sb2 = (const float*)d_in[23];

    const int* src = ei;
    const int* dst = ei + EE;

    float *h, *skip, *agg, *hcur, *als, *ald, *bnsum, *p0, *p1, *p2;
    int *cnt, *part, *bsum, *rowptr, *cursor, *csrc;
    cudaGetSymbolAddress((void**)&h, g_h);
    cudaGetSymbolAddress((void**)&skip, g_skip);
    cudaGetSymbolAddress((void**)&agg, g_agg);
    cudaGetSymbolAddress((void**)&hcur, g_hcur);
    cudaGetSymbolAddress((void**)&als, g_als);
    cudaGetSymbolAddress((void**)&ald, g_ald);
    cudaGetSymbolAddress((void**)&bnsum, g_bnsum);
    cudaGetSymbolAddress((void**)&p0, g_p0);
    cudaGetSymbolAddress((void**)&p1, g_p1);
    cudaGetSymbolAddress((void**)&p2, g_p2);
    cudaGetSymbolAddress((void**)&cnt, g_cnt);
    cudaGetSymbolAddress((void**)&part, g_part);
    cudaGetSymbolAddress((void**)&bsum, g_bsum);
    cudaGetSymbolAddress((void**)&rowptr, g_rowptr);
    cudaGetSymbolAddress((void**)&cursor, g_cursor);
    cudaGetSymbolAddress((void**)&csrc, g_csrc);

    dim3 gemm512(4, (NN + BM - 1) / BM);
    dim3 gemm240(2, (NN + BM - 1) / BM);
    int alBlocks = (NN * HEADS * 32 + 255) / 256;
    int nodeWarpBlocks = (NN * 32 + 255) / 256;
    int eBlocks = (EE + 255) / 256;

    // ===== CSR build =====
    cudaMemsetAsync(cnt, 0, NN * sizeof(int));
    count_kernel<<<eBlocks, 256>>>(dst, cnt);
    scan_blocks<<<NBLK, 256>>>(cnt, part, bsum);
    scan_totals<<<1, 128>>>(bsum);
    scan_add<<<(NN + 256) / 256, 256>>>(part, bsum, rowptr, cursor);
    fill_kernel<<<eBlocks, 256>>>(src, dst, cursor, csrc);

    // ===== pack weights =====
    pack_weights<<<480, 256>>>(w0, sw0, w1, sw1, w2, sw2, p0, p1, p2);

    // ===== Layer 0 =====
    hgemm_split<<<gemm512, 256>>>(x, p0, sb0, h, skip, NN, F_IN, 512, HC, HC);
    al_kernel<<<alBlocks, 256>>>(h, as0, ad0, als, ald, HID);
    gat_agg_kernel<<<nodeWarpBlocks, 256>>>(rowptr, csrc, h, als, ald, b0, skip, agg);
    cudaMemsetAsync(bnsum, 0, 2 * HC * sizeof(float));
    bn_stats_kernel<<<512, 256>>>(agg, bnsum);
    bn_apply_kernel<<<512, 256>>>(agg, bnsum, g0, be0, hcur);

    // ===== Layer 1 =====
    hgemm_split<<<gemm512, 256>>>(hcur, p1, sb1, h, skip, NN, HC, 512, HC, HC);
    al_kernel<<<alBlocks, 256>>>(h, as1, ad1, als, ald, HID);
    gat_agg_kernel<<<nodeWarpBlocks, 256>>>(rowptr, csrc, h, als, ald, b1, skip, agg);
    cudaMemsetAsync(bnsum, 0, 2 * HC * sizeof(float));
    bn_stats_kernel<<<512, 256>>>(agg, bnsum);
    bn_apply_kernel<<<512, 256>>>(agg, bnsum, g1, be1, hcur);

    // ===== Layer 2 =====
    hgemm_split<<<gemm240, 256>>>(hcur, p2, sb2, h, skip, NN, HC, NP2, L2OUT, NCLS);
    al_kernel<<<alBlocks, 256>>>(h, as2, ad2, als, ald, NCLS);
    gat_agg47_fused<<<nodeWarpBlocks, 256>>>(rowptr, csrc, h, (const float4*)als,
                                             (const float4*)ald, b2, skip, (float*)d_out);
}